// round 3
// baseline (speedup 1.0000x reference)
#include <cuda_runtime.h>
#include <cuda_bf16.h>
#include <math.h>

// ---------------- problem constants ----------------
#define Bb   4
#define Pp   2048
#define Dd   1024
#define Hh   16
#define KVh  8
#define HDd  64
#define Ff   4096
#define Ee   16
#define FEe  256
#define Tt   (Bb*Pp)          // 8192 tokens

// ---------------- scratch (device globals; no allocs allowed) ----------------
__device__ float g_h  [Tt * Dd];        // 32 MB  rmsnorm output (reused)
__device__ float g_q  [Tt * Hh  * HDd]; // 32 MB
__device__ float g_k  [Tt * KVh * HDd]; // 16 MB
__device__ float g_v  [Tt * KVh * HDd]; // 16 MB
__device__ float g_ao [Tt * Hh  * HDd]; // 32 MB  attention output
__device__ float g_t1 [Tt * Ff];        // 128 MB gate / fused t
__device__ float g_t2 [Tt * Ff];        // 128 MB up

// =====================================================================
// RMSNorm: one block per row of 1024, 256 threads * float4
// =====================================================================
__global__ void __launch_bounds__(256) rmsnorm_kernel(
    float* __restrict__ out, const float* __restrict__ x, const float* __restrict__ w)
{
    __shared__ float red[8];
    __shared__ float s_rms;
    const int row = blockIdx.x;
    const int t   = threadIdx.x;
    const float* xr = x + (long)row * Dd;
    float4 v = *(const float4*)(xr + t * 4);
    float ss = v.x*v.x + v.y*v.y + v.z*v.z + v.w*v.w;
    #pragma unroll
    for (int o = 16; o > 0; o >>= 1) ss += __shfl_xor_sync(0xffffffffu, ss, o);
    if ((t & 31) == 0) red[t >> 5] = ss;
    __syncthreads();
    if (t == 0) {
        float tot = 0.f;
        #pragma unroll
        for (int i = 0; i < 8; i++) tot += red[i];
        s_rms = rsqrtf(tot * (1.0f / Dd) + 1e-6f);
    }
    __syncthreads();
    const float rms = s_rms;
    float4 wv = *(const float4*)(w + t * 4);
    float4 o4;
    o4.x = v.x * rms * wv.x;
    o4.y = v.y * rms * wv.y;
    o4.z = v.z * rms * wv.z;
    o4.w = v.w * rms * wv.w;
    *(float4*)(out + (long)row * Dd + t * 4) = o4;
}

// =====================================================================
// Unified SGEMM: C[M,N] (=|+=) A[M,K] @ B + bias + Res
//   B column mapping: e = n / FEp, f = n % FEp, addr = B + e*eStride + k*FEp + f
//   -> normal row-major KxN:  FEp = N, eStride = 0
//   -> expert (E,D,FE):       FEp = FE, eStride = D*FE
// BM=BN=128, BK=16, 256 threads, 8x8 microtile. M,N multiples of 128, K of 16.
// =====================================================================
__global__ void __launch_bounds__(256) sgemm_kernel(
    float* __restrict__ C, const float* __restrict__ A, const float* __restrict__ Bm,
    const float* __restrict__ bias, const float* __restrict__ Res,
    int M, int N, int K, int FEp, long eStride, int accum)
{
    __shared__ float As[16][128];
    __shared__ float Bs[16][128];

    const int tid = threadIdx.x;
    const int n0  = blockIdx.x * 128;
    const int m0  = blockIdx.y * 128;
    const float* Bt = Bm + (long)(n0 / FEp) * eStride + (n0 % FEp);
    const float* At = A + (long)m0 * K;
    const int tx = tid & 15;
    const int ty = tid >> 4;

    // per-thread load coordinates (computed once)
    const int a_row0 = tid >> 2;             // 0..63  (then +64)
    const int a_kc   = (tid & 3) << 2;       // 0,4,8,12
    const int b_row0 = tid >> 5;             // 0..7   (then +8)
    const int b_col  = (tid & 31) << 2;      // 0..124
    const float* A0 = At + (long)a_row0 * K + a_kc;
    const float* A1 = At + (long)(a_row0 + 64) * K + a_kc;
    const float* B0 = Bt + (long)b_row0 * FEp + b_col;
    const long  bstep8 = (long)8 * FEp;

    float acc[8][8];
    #pragma unroll
    for (int i = 0; i < 8; i++)
        #pragma unroll
        for (int j = 0; j < 8; j++) acc[i][j] = 0.f;

    for (int k0 = 0; k0 < K; k0 += 16) {
        float4 va0 = *(const float4*)(A0 + k0);
        float4 va1 = *(const float4*)(A1 + k0);
        const float* bptr = B0 + (long)k0 * FEp;
        float4 vb0 = *(const float4*)(bptr);
        float4 vb1 = *(const float4*)(bptr + bstep8);
        As[a_kc + 0][a_row0]      = va0.x;
        As[a_kc + 1][a_row0]      = va0.y;
        As[a_kc + 2][a_row0]      = va0.z;
        As[a_kc + 3][a_row0]      = va0.w;
        As[a_kc + 0][a_row0 + 64] = va1.x;
        As[a_kc + 1][a_row0 + 64] = va1.y;
        As[a_kc + 2][a_row0 + 64] = va1.z;
        As[a_kc + 3][a_row0 + 64] = va1.w;
        *(float4*)&Bs[b_row0    ][b_col] = vb0;
        *(float4*)&Bs[b_row0 + 8][b_col] = vb1;
        __syncthreads();
        #pragma unroll
        for (int kk = 0; kk < 16; kk++) {
            float a[8], b[8];
            *(float4*)&a[0] = *(const float4*)&As[kk][ty * 8];
            *(float4*)&a[4] = *(const float4*)&As[kk][ty * 8 + 4];
            *(float4*)&b[0] = *(const float4*)&Bs[kk][tx * 8];
            *(float4*)&b[4] = *(const float4*)&Bs[kk][tx * 8 + 4];
            #pragma unroll
            for (int i = 0; i < 8; i++)
                #pragma unroll
                for (int j = 0; j < 8; j++) acc[i][j] += a[i] * b[j];
        }
        __syncthreads();
    }

    #pragma unroll
    for (int i = 0; i < 8; i++) {
        const int row = m0 + ty * 8 + i;
        #pragma unroll
        for (int j = 0; j < 8; j += 4) {
            const int  col = n0 + tx * 8 + j;
            const long idx = (long)row * N + col;
            float4 v;
            v.x = acc[i][j + 0]; v.y = acc[i][j + 1];
            v.z = acc[i][j + 2]; v.w = acc[i][j + 3];
            if (bias) {
                v.x += bias[col + 0]; v.y += bias[col + 1];
                v.z += bias[col + 2]; v.w += bias[col + 3];
            }
            if (Res) {
                float4 r = *(const float4*)(Res + idx);
                v.x += r.x; v.y += r.y; v.z += r.z; v.w += r.w;
            }
            if (accum) {
                float4 c = *(const float4*)(C + idx);
                v.x += c.x; v.y += c.y; v.z += c.z; v.w += c.w;
            }
            *(float4*)(C + idx) = v;
        }
    }
}

// =====================================================================
// RoPE (NeoX split-half), in place. Layout: [token][head][64].
// fp64 angle for accuracy (pos up to 2047 rad).
// =====================================================================
__global__ void rope_kernel(float* __restrict__ q, int nheads, int total)
{
    int idx = blockIdx.x * blockDim.x + threadIdx.x;
    if (idx >= total) return;
    int i    = idx & 31;
    int rest = idx >> 5;           // token*nheads + head
    int bp   = rest / nheads;
    int pos  = bp & (Pp - 1);
    double inv = pow(10000.0, -(double)i / 32.0);
    double ang = (double)pos * inv;
    double sd, cd;
    sincos(ang, &sd, &cd);
    float c = (float)cd, s = (float)sd;
    float* base = q + (long)rest * HDd + i;
    float v1 = base[0], v2 = base[32];
    base[0]  = v1 * c - v2 * s;
    base[32] = v2 * c + v1 * s;
}

// =====================================================================
// Flash attention fp32, causal, GQA (2 q-heads per kv-head).
// Block = (q-tile of 64, head, batch). 128 threads:
//   thread t -> row r = t>>1, half c0 = (t&1)*32 (same split for O dims).
// Dynamic smem: Qs[64][68] Ks[64][68] Ps[64][68] Vs[64][64]
// =====================================================================
#define ATTN_SMEM ((64*68*3 + 64*64) * 4)   // 68608 bytes

__global__ void __launch_bounds__(128) attn_kernel(
    float* __restrict__ O, const float* __restrict__ Qg,
    const float* __restrict__ Kg, const float* __restrict__ Vg)
{
    extern __shared__ float sm[];
    float* Qs = sm;                 // 64*68
    float* Ks = Qs + 64 * 68;
    float* Ps = Ks + 64 * 68;
    float* Vs = Ps + 64 * 68;       // 64*64

    const int qt = blockIdx.x, h = blockIdx.y, b = blockIdx.z;
    const int kvh = h >> 1;
    const int tid = threadIdx.x;
    const int r   = tid >> 1;
    const int c0  = (tid & 1) << 5;

    {   // load Q tile, pre-scaled by 1/sqrt(64)
        const float* Qb = Qg + (((long)b * Pp + qt * 64) * Hh + h) * HDd;
        #pragma unroll
        for (int l = 0; l < 8; l++) {
            int i = tid + l * 128;
            int row = i >> 4, dc = (i & 15) << 2;
            float4 v = *(const float4*)(Qb + (long)row * (Hh * HDd) + dc);
            float* qp = &Qs[row * 68 + dc];
            qp[0] = v.x * 0.125f; qp[1] = v.y * 0.125f;
            qp[2] = v.z * 0.125f; qp[3] = v.w * 0.125f;
        }
    }

    float m = -1e30f, lsum = 0.f;
    float Oa[32];
    #pragma unroll
    for (int d = 0; d < 32; d++) Oa[d] = 0.f;

    for (int j = 0; j <= qt; j++) {
        __syncthreads();   // prior-iteration smem reads done (also orders Q load)
        const float* Kb = Kg + (((long)b * Pp + j * 64) * KVh + kvh) * HDd;
        const float* Vb = Vg + (((long)b * Pp + j * 64) * KVh + kvh) * HDd;
        #pragma unroll
        for (int l = 0; l < 8; l++) {
            int i = tid + l * 128;
            int row = i >> 4, dc = (i & 15) << 2;
            float4 kv = *(const float4*)(Kb + (long)row * (KVh * HDd) + dc);
            float* kp = &Ks[row * 68 + dc];
            kp[0] = kv.x; kp[1] = kv.y; kp[2] = kv.z; kp[3] = kv.w;
            float4 vv = *(const float4*)(Vb + (long)row * (KVh * HDd) + dc);
            *(float4*)&Vs[row * 64 + dc] = vv;
        }
        __syncthreads();

        // S = Q K^T for this thread's 32 columns
        float s[32];
        #pragma unroll
        for (int c = 0; c < 32; c++) s[c] = 0.f;
        #pragma unroll
        for (int dc = 0; dc < 64; dc += 16) {
            float qv[16];
            #pragma unroll
            for (int t4 = 0; t4 < 4; t4++)
                *(float4*)&qv[t4 * 4] = *(const float4*)&Qs[r * 68 + dc + t4 * 4];
            #pragma unroll
            for (int c = 0; c < 32; c++) {
                const float4* kr = (const float4*)&Ks[(c0 + c) * 68 + dc];
                float4 k0 = kr[0], k1 = kr[1], k2 = kr[2], k3 = kr[3];
                s[c] += qv[0]*k0.x + qv[1]*k0.y + qv[2]*k0.z + qv[3]*k0.w
                      + qv[4]*k1.x + qv[5]*k1.y + qv[6]*k1.z + qv[7]*k1.w
                      + qv[8]*k2.x + qv[9]*k2.y + qv[10]*k2.z + qv[11]*k2.w
                      + qv[12]*k3.x + qv[13]*k3.y + qv[14]*k3.z + qv[15]*k3.w;
            }
        }
        if (j == qt) {  // causal mask on diagonal tile
            #pragma unroll
            for (int c = 0; c < 32; c++)
                if (c0 + c > r) s[c] = -1e30f;
        }

        // online softmax (pair of threads shares a row)
        float smax = -1e30f;
        #pragma unroll
        for (int c = 0; c < 32; c++) smax = fmaxf(smax, s[c]);
        smax = fmaxf(smax, __shfl_xor_sync(0xffffffffu, smax, 1));
        float mnew  = fmaxf(m, smax);
        float alpha = __expf(m - mnew);
        float psum  = 0.f;
        #pragma unroll
        for (int c = 0; c < 32; c++) {
            float p = __expf(s[c] - mnew);
            Ps[r * 68 + c0 + c] = p;
            psum += p;
        }
        psum += __shfl_xor_sync(0xffffffffu, psum, 1);
        lsum = lsum * alpha + psum;
        m = mnew;
        #pragma unroll
        for (int d = 0; d < 32; d++) Oa[d] *= alpha;
        __syncwarp();   // partner's Ps half visible (same warp)

        // O += P @ V for this thread's 32 dims
        #pragma unroll 2
        for (int c = 0; c < 64; c++) {
            float pv = Ps[r * 68 + c];
            const float4* vr = (const float4*)&Vs[c * 64 + c0];
            #pragma unroll
            for (int q4 = 0; q4 < 8; q4++) {
                float4 vv = vr[q4];
                Oa[q4 * 4 + 0] += pv * vv.x;
                Oa[q4 * 4 + 1] += pv * vv.y;
                Oa[q4 * 4 + 2] += pv * vv.z;
                Oa[q4 * 4 + 3] += pv * vv.w;
            }
        }
    }

    const float inv_l = 1.f / lsum;
    float* Ob = O + (((long)b * Pp + qt * 64 + r) * Hh + h) * HDd + c0;
    #pragma unroll
    for (int d = 0; d < 32; d++) Ob[d] = Oa[d] * inv_l;
}

// =====================================================================
// t = silu(g) * u  (* mask[token, col>>8] if mask)   elementwise, in place ok
// =====================================================================
__global__ void silu_mul_kernel(float* __restrict__ t, const float* __restrict__ g,
    const float* __restrict__ u, const float* __restrict__ mask, int Ncols)
{
    long i = (long)blockIdx.x * blockDim.x + threadIdx.x;
    float gv = g[i], uv = u[i];
    float v = gv / (1.f + __expf(-gv)) * uv;
    if (mask) {
        int row = (int)(i / Ncols);
        int col = (int)(i - (long)row * Ncols);
        v *= mask[row * Ee + (col >> 8)];    // FE = 256
    }
    t[i] = v;
}

// =====================================================================
// launcher
// =====================================================================
extern "C" void kernel_launch(void* const* d_in, const int* in_sizes, int n_in,
                              void* d_out, int out_size)
{
    const float* x    = (const float*)d_in[0];
    const float* emsk = (const float*)d_in[1];
    const float* ln1  = (const float*)d_in[2];
    const float* wq   = (const float*)d_in[3];
    const float* bq   = (const float*)d_in[4];
    const float* wk   = (const float*)d_in[5];
    const float* bk   = (const float*)d_in[6];
    const float* wv   = (const float*)d_in[7];
    const float* bv   = (const float*)d_in[8];
    const float* wo   = (const float*)d_in[9];
    const float* ln2  = (const float*)d_in[10];
    const float* wg   = (const float*)d_in[11];
    const float* wu   = (const float*)d_in[12];
    const float* wd   = (const float*)d_in[13];
    const float* weg  = (const float*)d_in[14];
    const float* weu  = (const float*)d_in[15];
    const float* wed  = (const float*)d_in[16];
    float* out = (float*)d_out;

    // Non-launch API work first (capture-legal; enqueues nothing).
    float *ph, *pq, *pk, *pv, *pao, *pt1, *pt2;
    cudaGetSymbolAddress((void**)&ph,  g_h);
    cudaGetSymbolAddress((void**)&pq,  g_q);
    cudaGetSymbolAddress((void**)&pk,  g_k);
    cudaGetSymbolAddress((void**)&pv,  g_v);
    cudaGetSymbolAddress((void**)&pao, g_ao);
    cudaGetSymbolAddress((void**)&pt1, g_t1);
    cudaGetSymbolAddress((void**)&pt2, g_t2);
    cudaFuncSetAttribute(attn_kernel, cudaFuncAttributeMaxDynamicSharedMemorySize, ATTN_SMEM);

    const int MT = Tt / 128;  // 64 M-tiles

    // 1. h = rmsnorm(x)
    rmsnorm_kernel<<<Tt, 256>>>(ph, x, ln1);
    // 2. q,k,v projections (+bias)
    sgemm_kernel<<<dim3(1024/128, MT), 256>>>(pq, ph, wq, bq, nullptr, Tt, 1024, Dd, 1024, 0, 0);
    sgemm_kernel<<<dim3( 512/128, MT), 256>>>(pk, ph, wk, bk, nullptr, Tt,  512, Dd,  512, 0, 0);
    sgemm_kernel<<<dim3( 512/128, MT), 256>>>(pv, ph, wv, bv, nullptr, Tt,  512, Dd,  512, 0, 0);
    // 3. rope
    {
        int pq_n = Tt * Hh  * 32;
        int pk_n = Tt * KVh * 32;
        rope_kernel<<<pq_n / 256, 256>>>(pq, Hh,  pq_n);
        rope_kernel<<<pk_n / 256, 256>>>(pk, KVh, pk_n);
    }
    // 4. flash attention
    attn_kernel<<<dim3(Pp / 64, Hh, Bb), 128, ATTN_SMEM>>>(pao, pq, pk, pv);
    // 5. out = x + attn @ wo   (residual fused)
    sgemm_kernel<<<dim3(1024/128, MT), 256>>>(out, pao, wo, nullptr, x, Tt, Dd, Hh * HDd, Dd, 0, 0);
    // 6. h2 = rmsnorm(out)
    rmsnorm_kernel<<<Tt, 256>>>(ph, out, ln2);
    // 7. dense MLP
    sgemm_kernel<<<dim3(Ff/128, MT), 256>>>(pt1, ph, wg, nullptr, nullptr, Tt, Ff, Dd, Ff, 0, 0);
    sgemm_kernel<<<dim3(Ff/128, MT), 256>>>(pt2, ph, wu, nullptr, nullptr, Tt, Ff, Dd, Ff, 0, 0);
    silu_mul_kernel<<<(Tt * Ff) / 256, 256>>>(pt1, pt1, pt2, nullptr, Ff);
    sgemm_kernel<<<dim3(1024/128, MT), 256>>>(out, pt1, wd, nullptr, nullptr, Tt, Dd, Ff, Dd, 0, 1);
    // 8. experts (all 16 dense; mask folded into t)
    const int NE = Ee * FEe;  // 4096
    sgemm_kernel<<<dim3(NE/128, MT), 256>>>(pt1, ph, weg, nullptr, nullptr, Tt, NE, Dd, FEe, (long)Dd * FEe, 0);
    sgemm_kernel<<<dim3(NE/128, MT), 256>>>(pt2, ph, weu, nullptr, nullptr, Tt, NE, Dd, FEe, (long)Dd * FEe, 0);
    silu_mul_kernel<<<(Tt * NE) / 256, 256>>>(pt1, pt1, pt2, emsk, NE);
    // 9. routed down-proj: we_down (E,FE,D) == row-major (4096,1024); accumulate
    sgemm_kernel<<<dim3(1024/128, MT), 256>>>(out, pt1, wed, nullptr, nullptr, Tt, Dd, NE, Dd, 0, 1);
}

// round 4
// speedup vs baseline: 1.8622x; 1.8622x over previous
#include <cuda_runtime.h>
#include <cuda_bf16.h>
#include <math.h>
#include <stdint.h>

// ---------------- problem constants ----------------
#define Bb   4
#define Pp   2048
#define Dd   1024
#define Hh   16
#define KVh  8
#define HDd  64
#define Ff   4096
#define Ee   16
#define FEe  256
#define Tt   (Bb*Pp)          // 8192 tokens

// ---------------- scratch (device globals; no allocs allowed) ----------------
__device__ float g_h  [Tt * Dd];        // 32 MB  rmsnorm output (reused)
__device__ float g_q  [Tt * Hh  * HDd]; // 32 MB
__device__ float g_k  [Tt * KVh * HDd]; // 16 MB
__device__ float g_v  [Tt * KVh * HDd]; // 16 MB
__device__ float g_ao [Tt * Hh  * HDd]; // 32 MB  attention output
__device__ float g_t1 [Tt * Ff];        // 128 MB gate / fused t
__device__ float g_t2 [Tt * Ff];        // 128 MB up

// =====================================================================
// RMSNorm: one block per row of 1024, 256 threads * float4
// =====================================================================
__global__ void __launch_bounds__(256) rmsnorm_kernel(
    float* __restrict__ out, const float* __restrict__ x, const float* __restrict__ w)
{
    __shared__ float red[8];
    __shared__ float s_rms;
    const int row = blockIdx.x;
    const int t   = threadIdx.x;
    const float* xr = x + (long)row * Dd;
    float4 v = *(const float4*)(xr + t * 4);
    float ss = v.x*v.x + v.y*v.y + v.z*v.z + v.w*v.w;
    #pragma unroll
    for (int o = 16; o > 0; o >>= 1) ss += __shfl_xor_sync(0xffffffffu, ss, o);
    if ((t & 31) == 0) red[t >> 5] = ss;
    __syncthreads();
    if (t == 0) {
        float tot = 0.f;
        #pragma unroll
        for (int i = 0; i < 8; i++) tot += red[i];
        s_rms = rsqrtf(tot * (1.0f / Dd) + 1e-6f);
    }
    __syncthreads();
    const float rms = s_rms;
    float4 wv = *(const float4*)(w + t * 4);
    float4 o4;
    o4.x = v.x * rms * wv.x;
    o4.y = v.y * rms * wv.y;
    o4.z = v.z * rms * wv.z;
    o4.w = v.w * rms * wv.w;
    *(float4*)(out + (long)row * Dd + t * 4) = o4;
}

// =====================================================================
// TF32 tensor-core GEMM: C[M,N] (=|+=) A[M,K] @ B + bias + Res
//   B column mapping: e = n / FEp, f = n % FEp, addr = B + e*eStride + k*FEp + f
//   -> normal row-major KxN:  FEp = N, eStride = 0
//   -> expert (E,D,FE):       FEp = FE, eStride = D*FE
// BM=BN=128, BK=32, 256 threads (8 warps, 4x2), warp tile 32x64 via
// m16n8k8 mma.sync. fp32 accumulate, cvt.rna tf32 inputs.
// M,N multiples of 128, K of 32.
// =====================================================================
__device__ __forceinline__ uint32_t f2tf32(float f) {
    uint32_t r;
    asm("cvt.rna.tf32.f32 %0, %1;" : "=r"(r) : "f"(f));
    return r;
}

#define MMA_TF32(d, a, b)                                                     \
  asm volatile("mma.sync.aligned.m16n8k8.row.col.f32.tf32.tf32.f32 "          \
    "{%0,%1,%2,%3}, {%4,%5,%6,%7}, {%8,%9}, {%0,%1,%2,%3};"                   \
    : "+f"((d)[0]), "+f"((d)[1]), "+f"((d)[2]), "+f"((d)[3])                  \
    : "r"((a)[0]), "r"((a)[1]), "r"((a)[2]), "r"((a)[3]),                     \
      "r"((b)[0]), "r"((b)[1]))

__global__ void __launch_bounds__(256) sgemm_kernel(
    float* __restrict__ C, const float* __restrict__ A, const float* __restrict__ Bm,
    const float* __restrict__ bias, const float* __restrict__ Res,
    int M, int N, int K, int FEp, long eStride, int accum)
{
    __shared__ uint32_t As[32][132];   // [k][m], tf32 bits
    __shared__ uint32_t Bs[32][132];   // [k][n], tf32 bits

    const int tid = threadIdx.x;
    const int n0  = blockIdx.x * 128;
    const int m0  = blockIdx.y * 128;
    const float* Bt = Bm + (long)(n0 / FEp) * eStride + (n0 % FEp);
    const float* At = A + (long)m0 * K;

    const int wid  = tid >> 5;
    const int lane = tid & 31;
    const int grp  = lane >> 2;     // 0..7
    const int tig  = lane & 3;      // 0..3
    const int mw   = (wid & 3) * 32;
    const int nw   = (wid >> 2) * 64;

    float acc[2][8][4];
    #pragma unroll
    for (int t = 0; t < 2; t++)
        #pragma unroll
        for (int s = 0; s < 8; s++)
            #pragma unroll
            for (int i = 0; i < 4; i++) acc[t][s][i] = 0.f;

    for (int k0 = 0; k0 < K; k0 += 32) {
        __syncthreads();   // previous-iteration smem reads complete
        #pragma unroll
        for (int l = 0; l < 4; l++) {
            int ch  = tid + l * 256;
            int ar  = ch >> 3;               // 0..127
            int akc = (ch & 7) << 2;         // 0..28
            float4 va = *(const float4*)(At + (long)ar * K + k0 + akc);
            As[akc + 0][ar] = f2tf32(va.x);
            As[akc + 1][ar] = f2tf32(va.y);
            As[akc + 2][ar] = f2tf32(va.z);
            As[akc + 3][ar] = f2tf32(va.w);
            int br = ch >> 5;                // 0..31
            int bc = (ch & 31) << 2;         // 0..124
            float4 vb = *(const float4*)(Bt + (long)(k0 + br) * FEp + bc);
            Bs[br][bc + 0] = f2tf32(vb.x);
            Bs[br][bc + 1] = f2tf32(vb.y);
            Bs[br][bc + 2] = f2tf32(vb.z);
            Bs[br][bc + 3] = f2tf32(vb.w);
        }
        __syncthreads();

        #pragma unroll
        for (int kk = 0; kk < 32; kk += 8) {
            uint32_t a[2][4], b[8][2];
            #pragma unroll
            for (int t = 0; t < 2; t++) {
                int m = mw + t * 16 + grp;
                a[t][0] = As[kk + tig    ][m];
                a[t][1] = As[kk + tig    ][m + 8];
                a[t][2] = As[kk + tig + 4][m];
                a[t][3] = As[kk + tig + 4][m + 8];
            }
            #pragma unroll
            for (int s = 0; s < 8; s++) {
                int n = nw + s * 8 + grp;
                b[s][0] = Bs[kk + tig    ][n];
                b[s][1] = Bs[kk + tig + 4][n];
            }
            #pragma unroll
            for (int t = 0; t < 2; t++)
                #pragma unroll
                for (int s = 0; s < 8; s++)
                    MMA_TF32(acc[t][s], a[t], b[s]);
        }
    }

    // epilogue: c0,c1 -> (row, col..col+1); c2,c3 -> (row+8, col..col+1)
    #pragma unroll
    for (int t = 0; t < 2; t++) {
        #pragma unroll
        for (int s = 0; s < 8; s++) {
            const int row = m0 + mw + t * 16 + grp;
            const int col = n0 + nw + s * 8 + tig * 2;
            float2 bv = make_float2(0.f, 0.f);
            if (bias) bv = *(const float2*)(bias + col);
            #pragma unroll
            for (int half = 0; half < 2; half++) {
                const int  r   = row + half * 8;
                const long idx = (long)r * N + col;
                float2 v;
                v.x = acc[t][s][half * 2 + 0] + bv.x;
                v.y = acc[t][s][half * 2 + 1] + bv.y;
                if (Res) {
                    float2 rr = *(const float2*)(Res + idx);
                    v.x += rr.x; v.y += rr.y;
                }
                if (accum) {
                    float2 cc = *(const float2*)(C + idx);
                    v.x += cc.x; v.y += cc.y;
                }
                *(float2*)(C + idx) = v;
            }
        }
    }
}

// =====================================================================
// RoPE (NeoX split-half), in place. Layout: [token][head][64].
// fp64 angle for accuracy (pos up to 2047 rad).
// =====================================================================
__global__ void rope_kernel(float* __restrict__ q, int nheads, int total)
{
    int idx = blockIdx.x * blockDim.x + threadIdx.x;
    if (idx >= total) return;
    int i    = idx & 31;
    int rest = idx >> 5;           // token*nheads + head
    int bp   = rest / nheads;
    int pos  = bp & (Pp - 1);
    double inv = pow(10000.0, -(double)i / 32.0);
    double ang = (double)pos * inv;
    double sd, cd;
    sincos(ang, &sd, &cd);
    float c = (float)cd, s = (float)sd;
    float* base = q + (long)rest * HDd + i;
    float v1 = base[0], v2 = base[32];
    base[0]  = v1 * c - v2 * s;
    base[32] = v2 * c + v1 * s;
}

// =====================================================================
// Flash attention fp32, causal, GQA (2 q-heads per kv-head).
// Block = (q-tile of 64, head, batch). 128 threads:
//   thread t -> row r = t>>1, half c0 = (t&1)*32 (same split for O dims).
// Dynamic smem: Qs[64][68] Ks[64][68] Ps[64][68] Vs[64][64]
// =====================================================================
#define ATTN_SMEM ((64*68*3 + 64*64) * 4)   // 68608 bytes

__global__ void __launch_bounds__(128) attn_kernel(
    float* __restrict__ O, const float* __restrict__ Qg,
    const float* __restrict__ Kg, const float* __restrict__ Vg)
{
    extern __shared__ float sm[];
    float* Qs = sm;                 // 64*68
    float* Ks = Qs + 64 * 68;
    float* Ps = Ks + 64 * 68;
    float* Vs = Ps + 64 * 68;       // 64*64

    const int qt = blockIdx.x, h = blockIdx.y, b = blockIdx.z;
    const int kvh = h >> 1;
    const int tid = threadIdx.x;
    const int r   = tid >> 1;
    const int c0  = (tid & 1) << 5;

    {   // load Q tile, pre-scaled by 1/sqrt(64)
        const float* Qb = Qg + (((long)b * Pp + qt * 64) * Hh + h) * HDd;
        #pragma unroll
        for (int l = 0; l < 8; l++) {
            int i = tid + l * 128;
            int row = i >> 4, dc = (i & 15) << 2;
            float4 v = *(const float4*)(Qb + (long)row * (Hh * HDd) + dc);
            float* qp = &Qs[row * 68 + dc];
            qp[0] = v.x * 0.125f; qp[1] = v.y * 0.125f;
            qp[2] = v.z * 0.125f; qp[3] = v.w * 0.125f;
        }
    }

    float m = -1e30f, lsum = 0.f;
    float Oa[32];
    #pragma unroll
    for (int d = 0; d < 32; d++) Oa[d] = 0.f;

    for (int j = 0; j <= qt; j++) {
        __syncthreads();   // prior-iteration smem reads done (also orders Q load)
        const float* Kb = Kg + (((long)b * Pp + j * 64) * KVh + kvh) * HDd;
        const float* Vb = Vg + (((long)b * Pp + j * 64) * KVh + kvh) * HDd;
        #pragma unroll
        for (int l = 0; l < 8; l++) {
            int i = tid + l * 128;
            int row = i >> 4, dc = (i & 15) << 2;
            float4 kv = *(const float4*)(Kb + (long)row * (KVh * HDd) + dc);
            float* kp = &Ks[row * 68 + dc];
            kp[0] = kv.x; kp[1] = kv.y; kp[2] = kv.z; kp[3] = kv.w;
            float4 vv = *(const float4*)(Vb + (long)row * (KVh * HDd) + dc);
            *(float4*)&Vs[row * 64 + dc] = vv;
        }
        __syncthreads();

        // S = Q K^T for this thread's 32 columns
        float s[32];
        #pragma unroll
        for (int c = 0; c < 32; c++) s[c] = 0.f;
        #pragma unroll
        for (int dc = 0; dc < 64; dc += 16) {
            float qv[16];
            #pragma unroll
            for (int t4 = 0; t4 < 4; t4++)
                *(float4*)&qv[t4 * 4] = *(const float4*)&Qs[r * 68 + dc + t4 * 4];
            #pragma unroll
            for (int c = 0; c < 32; c++) {
                const float4* kr = (const float4*)&Ks[(c0 + c) * 68 + dc];
                float4 k0 = kr[0], k1 = kr[1], k2 = kr[2], k3 = kr[3];
                s[c] += qv[0]*k0.x + qv[1]*k0.y + qv[2]*k0.z + qv[3]*k0.w
                      + qv[4]*k1.x + qv[5]*k1.y + qv[6]*k1.z + qv[7]*k1.w
                      + qv[8]*k2.x + qv[9]*k2.y + qv[10]*k2.z + qv[11]*k2.w
                      + qv[12]*k3.x + qv[13]*k3.y + qv[14]*k3.z + qv[15]*k3.w;
            }
        }
        if (j == qt) {  // causal mask on diagonal tile
            #pragma unroll
            for (int c = 0; c < 32; c++)
                if (c0 + c > r) s[c] = -1e30f;
        }

        // online softmax (pair of threads shares a row)
        float smax = -1e30f;
        #pragma unroll
        for (int c = 0; c < 32; c++) smax = fmaxf(smax, s[c]);
        smax = fmaxf(smax, __shfl_xor_sync(0xffffffffu, smax, 1));
        float mnew  = fmaxf(m, smax);
        float alpha = __expf(m - mnew);
        float psum  = 0.f;
        #pragma unroll
        for (int c = 0; c < 32; c++) {
            float p = __expf(s[c] - mnew);
            Ps[r * 68 + c0 + c] = p;
            psum += p;
        }
        psum += __shfl_xor_sync(0xffffffffu, psum, 1);
        lsum = lsum * alpha + psum;
        m = mnew;
        #pragma unroll
        for (int d = 0; d < 32; d++) Oa[d] *= alpha;
        __syncwarp();   // partner's Ps half visible (same warp)

        // O += P @ V for this thread's 32 dims
        #pragma unroll 2
        for (int c = 0; c < 64; c++) {
            float pv = Ps[r * 68 + c];
            const float4* vr = (const float4*)&Vs[c * 64 + c0];
            #pragma unroll
            for (int q4 = 0; q4 < 8; q4++) {
                float4 vv = vr[q4];
                Oa[q4 * 4 + 0] += pv * vv.x;
                Oa[q4 * 4 + 1] += pv * vv.y;
                Oa[q4 * 4 + 2] += pv * vv.z;
                Oa[q4 * 4 + 3] += pv * vv.w;
            }
        }
    }

    const float inv_l = 1.f / lsum;
    float* Ob = O + (((long)b * Pp + qt * 64 + r) * Hh + h) * HDd + c0;
    #pragma unroll
    for (int d = 0; d < 32; d++) Ob[d] = Oa[d] * inv_l;
}

// =====================================================================
// t = silu(g) * u  (* mask[token, col>>8] if mask)   elementwise, in place ok
// =====================================================================
__global__ void silu_mul_kernel(float* __restrict__ t, const float* __restrict__ g,
    const float* __restrict__ u, const float* __restrict__ mask, int Ncols)
{
    long i = (long)blockIdx.x * blockDim.x + threadIdx.x;
    float gv = g[i], uv = u[i];
    float v = gv / (1.f + __expf(-gv)) * uv;
    if (mask) {
        int row = (int)(i / Ncols);
        int col = (int)(i - (long)row * Ncols);
        v *= mask[row * Ee + (col >> 8)];    // FE = 256
    }
    t[i] = v;
}

// =====================================================================
// launcher
// =====================================================================
extern "C" void kernel_launch(void* const* d_in, const int* in_sizes, int n_in,
                              void* d_out, int out_size)
{
    const float* x    = (const float*)d_in[0];
    const float* emsk = (const float*)d_in[1];
    const float* ln1  = (const float*)d_in[2];
    const float* wq   = (const float*)d_in[3];
    const float* bq   = (const float*)d_in[4];
    const float* wk   = (const float*)d_in[5];
    const float* bk   = (const float*)d_in[6];
    const float* wv   = (const float*)d_in[7];
    const float* bv   = (const float*)d_in[8];
    const float* wo   = (const float*)d_in[9];
    const float* ln2  = (const float*)d_in[10];
    const float* wg   = (const float*)d_in[11];
    const float* wu   = (const float*)d_in[12];
    const float* wd   = (const float*)d_in[13];
    const float* weg  = (const float*)d_in[14];
    const float* weu  = (const float*)d_in[15];
    const float* wed  = (const float*)d_in[16];
    float* out = (float*)d_out;

    // Non-launch API work first (capture-legal; enqueues nothing).
    float *ph, *pq, *pk, *pv, *pao, *pt1, *pt2;
    cudaGetSymbolAddress((void**)&ph,  g_h);
    cudaGetSymbolAddress((void**)&pq,  g_q);
    cudaGetSymbolAddress((void**)&pk,  g_k);
    cudaGetSymbolAddress((void**)&pv,  g_v);
    cudaGetSymbolAddress((void**)&pao, g_ao);
    cudaGetSymbolAddress((void**)&pt1, g_t1);
    cudaGetSymbolAddress((void**)&pt2, g_t2);
    cudaFuncSetAttribute(attn_kernel, cudaFuncAttributeMaxDynamicSharedMemorySize, ATTN_SMEM);

    const int MT = Tt / 128;  // 64 M-tiles

    // 1. h = rmsnorm(x)
    rmsnorm_kernel<<<Tt, 256>>>(ph, x, ln1);
    // 2. q,k,v projections (+bias)
    sgemm_kernel<<<dim3(1024/128, MT), 256>>>(pq, ph, wq, bq, nullptr, Tt, 1024, Dd, 1024, 0, 0);
    sgemm_kernel<<<dim3( 512/128, MT), 256>>>(pk, ph, wk, bk, nullptr, Tt,  512, Dd,  512, 0, 0);
    sgemm_kernel<<<dim3( 512/128, MT), 256>>>(pv, ph, wv, bv, nullptr, Tt,  512, Dd,  512, 0, 0);
    // 3. rope
    {
        int pq_n = Tt * Hh  * 32;
        int pk_n = Tt * KVh * 32;
        rope_kernel<<<pq_n / 256, 256>>>(pq, Hh,  pq_n);
        rope_kernel<<<pk_n / 256, 256>>>(pk, KVh, pk_n);
    }
    // 4. flash attention
    attn_kernel<<<dim3(Pp / 64, Hh, Bb), 128, ATTN_SMEM>>>(pao, pq, pk, pv);
    // 5. out = x + attn @ wo   (residual fused)
    sgemm_kernel<<<dim3(1024/128, MT), 256>>>(out, pao, wo, nullptr, x, Tt, Dd, Hh * HDd, Dd, 0, 0);
    // 6. h2 = rmsnorm(out)
    rmsnorm_kernel<<<Tt, 256>>>(ph, out, ln2);
    // 7. dense MLP
    sgemm_kernel<<<dim3(Ff/128, MT), 256>>>(pt1, ph, wg, nullptr, nullptr, Tt, Ff, Dd, Ff, 0, 0);
    sgemm_kernel<<<dim3(Ff/128, MT), 256>>>(pt2, ph, wu, nullptr, nullptr, Tt, Ff, Dd, Ff, 0, 0);
    silu_mul_kernel<<<(Tt * Ff) / 256, 256>>>(pt1, pt1, pt2, nullptr, Ff);
    sgemm_kernel<<<dim3(1024/128, MT), 256>>>(out, pt1, wd, nullptr, nullptr, Tt, Dd, Ff, Dd, 0, 1);
    // 8. experts (all 16 dense; mask folded into t)
    const int NE = Ee * FEe;  // 4096
    sgemm_kernel<<<dim3(NE/128, MT), 256>>>(pt1, ph, weg, nullptr, nullptr, Tt, NE, Dd, FEe, (long)Dd * FEe, 0);
    sgemm_kernel<<<dim3(NE/128, MT), 256>>>(pt2, ph, weu, nullptr, nullptr, Tt, NE, Dd, FEe, (long)Dd * FEe, 0);
    silu_mul_kernel<<<(Tt * NE) / 256, 256>>>(pt1, pt1, pt2, emsk, NE);
    // 9. routed down-proj: we_down (E,FE,D) == row-major (4096,1024); accumulate
    sgemm_kernel<<<dim3(1024/128, MT), 256>>>(out, pt1, wed, nullptr, nullptr, Tt, Dd, NE, Dd, 0, 1);
}